// round 2
// baseline (speedup 1.0000x reference)
#include <cuda_runtime.h>
#include <math.h>

// Problem constants (match reference)
#define BATCH 4
#define NPTS  300000
#define NX_   540
#define NY_   540
#define NZ_   8
#define NV_   (NX_ * NY_ * NZ_)          // 2,332,800
#define NFEAT 5

// Output layout (tuple flattened in order, all float32):
//   [0, BATCH*NV_*NFEAT)                         voxels (means)
//   [BATCH*NV_*NFEAT, BATCH*NV_*NFEAT+BATCH*NV_) counts
//   last 3 elements                              shape = {540, 540, 8}

__global__ void shape_init_kernel(float* __restrict__ out, size_t shape_off) {
    if (threadIdx.x == 0 && blockIdx.x == 0) {
        out[shape_off + 0] = 540.0f;
        out[shape_off + 1] = 540.0f;
        out[shape_off + 2] = 8.0f;
    }
}

__global__ void scatter_kernel(const float* __restrict__ pts,
                               float* __restrict__ sums,
                               float* __restrict__ cnts) {
    int idx = blockIdx.x * blockDim.x + threadIdx.x;
    if (idx >= BATCH * NPTS) return;

    const float* p = pts + (size_t)idx * NFEAT;
    float x  = p[0];
    float y  = p[1];
    float z  = p[2];
    float f3 = p[3];
    float f4 = p[4];

    // keep = all(xyz >= LO) & all(xyz <= HI), inclusive both sides
    bool keep = (x >= -54.0f) & (x <= 54.0f) &
                (y >= -54.0f) & (y <= 54.0f) &
                (z >= -5.0f)  & (z <= 3.0f);
    if (!keep) return;

    // Reference (XLA) computes (xyz - LO) / VOX as (xyz - LO) * (1/VOX) with
    // the reciprocal folded to the nearest fp32: 1/0.2f -> exactly 5.0f.
    // Match that bit-for-bit (a plain IEEE division differs by 1 ulp for some
    // inputs and flips boundary points into the wrong voxel).
    int cx = (int)floorf((x + 54.0f) * 5.0f);
    int cy = (int)floorf((y + 54.0f) * 5.0f);
    int cz = (int)floorf(z + 5.0f);          // VOX_z = 1.0
    cx = min(max(cx, 0), NX_ - 1);
    cy = min(max(cy, 0), NY_ - 1);
    cz = min(max(cz, 0), NZ_ - 1);

    int b = idx / NPTS;
    size_t lin = ((size_t)cz * NY_ + (size_t)cy) * NX_ + (size_t)cx;
    size_t v = (size_t)b * NV_ + lin;

    float* s = sums + v * NFEAT;
    atomicAdd(s + 0, x);
    atomicAdd(s + 1, y);
    atomicAdd(s + 2, z);
    atomicAdd(s + 3, f3);
    atomicAdd(s + 4, f4);
    atomicAdd(cnts + v, 1.0f);
}

// After zero-init: cnt==0 -> 0/max(0,1)=0 already stored; cnt==1 -> sum/1 is
// already the mean. Only voxels with cnt>=2 need the divide, keeping finalize
// traffic to the counts read + sparse RMW of multi-point voxels.
__global__ void finalize_kernel(float* __restrict__ sums,
                                const float* __restrict__ cnts) {
    size_t i = (size_t)blockIdx.x * blockDim.x + threadIdx.x;
    if (i >= (size_t)BATCH * NV_) return;
    float c = cnts[i];
    if (c > 1.5f) {
        float* s = sums + i * NFEAT;
        #pragma unroll
        for (int f = 0; f < NFEAT; f++)
            s[f] = __fdiv_rn(s[f], c);
    }
}

extern "C" void kernel_launch(void* const* d_in, const int* in_sizes, int n_in,
                              void* d_out, int out_size) {
    const float* pts = (const float*)d_in[0];
    float* out = (float*)d_out;

    const size_t n_sums  = (size_t)BATCH * NV_ * NFEAT;   // 46,656,000
    const size_t n_cnts  = (size_t)BATCH * NV_;           //  9,331,200
    const size_t shape_off = n_sums + n_cnts;             // 55,987,200

    float* sums = out;
    float* cnts = out + n_sums;

    // Zero the entire output (memset node in the graph). Zeros ARE the correct
    // value for every unoccupied voxel.
    cudaMemsetAsync(d_out, 0, (size_t)out_size * sizeof(float), 0);

    shape_init_kernel<<<1, 32>>>(out, shape_off);

    const int threads = 256;
    int n_points = BATCH * NPTS;
    scatter_kernel<<<(n_points + threads - 1) / threads, threads>>>(pts, sums, cnts);

    size_t n_vox = (size_t)BATCH * NV_;
    finalize_kernel<<<(unsigned)((n_vox + threads - 1) / threads), threads>>>(sums, cnts);
}

// round 3
// speedup vs baseline: 1.0725x; 1.0725x over previous
#include <cuda_runtime.h>
#include <math.h>

// Problem constants (match reference)
#define BATCH 4
#define NPTS  300000
#define NX_   540
#define NY_   540
#define NZ_   8
#define NV_   (NX_ * NY_ * NZ_)          // 2,332,800
#define NFEAT 5

// Output layout (tuple flattened in order, all float32):
//   [0, BATCH*NV_*NFEAT)                         voxels (means)   46,656,000
//   [.., +BATCH*NV_)                             counts            9,331,200
//   last 3 elements                              shape = {540, 540, 8}
// Total 55,987,203 floats. The first 55,987,200 are divisible by 4 ->
// exactly 13,996,800 float4 stores zero the data region; the 3-float tail is
// the shape constants.

#define N_DATA4 13996800u   // (BATCH*NV_*(NFEAT+1)) / 4

__global__ void zero_init_kernel(float4* __restrict__ out4,
                                 float* __restrict__ out) {
    unsigned i = blockIdx.x * blockDim.x + threadIdx.x;
    if (i < N_DATA4) {
        out4[i] = make_float4(0.f, 0.f, 0.f, 0.f);
    }
    if (i == 0) {
        const size_t shape_off = (size_t)N_DATA4 * 4;
        out[shape_off + 0] = 540.0f;
        out[shape_off + 1] = 540.0f;
        out[shape_off + 2] = 8.0f;
    }
}

__global__ void scatter_kernel(const float* __restrict__ pts,
                               float* __restrict__ sums,
                               float* __restrict__ cnts) {
    int pi = blockIdx.x * blockDim.x + threadIdx.x;
    if (pi >= NPTS) return;
    int b = blockIdx.y;

    const float* p = pts + ((size_t)b * NPTS + pi) * NFEAT;
    float x  = p[0];
    float y  = p[1];
    float z  = p[2];
    float f3 = p[3];
    float f4 = p[4];

    // keep = all(xyz >= LO) & all(xyz <= HI), inclusive both sides
    bool keep = (x >= -54.0f) & (x <= 54.0f) &
                (y >= -54.0f) & (y <= 54.0f) &
                (z >= -5.0f)  & (z <= 3.0f);
    if (!keep) return;

    // Reference (XLA) computes (xyz - LO) / VOX as multiply by the rounded
    // reciprocal: 1/0.2f folds to exactly 5.0f. Match bit-for-bit.
    int cx = (int)floorf((x + 54.0f) * 5.0f);
    int cy = (int)floorf((y + 54.0f) * 5.0f);
    int cz = (int)floorf(z + 5.0f);          // VOX_z = 1.0
    cx = min(max(cx, 0), NX_ - 1);
    cy = min(max(cy, 0), NY_ - 1);
    cz = min(max(cz, 0), NZ_ - 1);

    size_t lin = ((size_t)cz * NY_ + (size_t)cy) * NX_ + (size_t)cx;
    size_t v = (size_t)b * NV_ + lin;

    float* s = sums + v * NFEAT;
    atomicAdd(s + 0, x);
    atomicAdd(s + 1, y);
    atomicAdd(s + 2, z);
    atomicAdd(s + 3, f3);
    atomicAdd(s + 4, f4);
    atomicAdd(cnts + v, 1.0f);
}

// After zero-init: cnt==0 -> 0 already stored; cnt==1 -> sum/1 is already the
// mean. Only voxels with cnt>=2 need the divide. float4 count reads: one
// thread handles 4 voxels (BATCH*NV_ divisible by 4).
__global__ void finalize_kernel(float* __restrict__ sums,
                                const float4* __restrict__ cnts4) {
    unsigned i = blockIdx.x * blockDim.x + threadIdx.x;
    const unsigned n4 = (unsigned)((size_t)BATCH * NV_ / 4);
    if (i >= n4) return;
    float4 c = cnts4[i];
    size_t v0 = (size_t)i * 4;
    float cs[4] = {c.x, c.y, c.z, c.w};
    #pragma unroll
    for (int k = 0; k < 4; k++) {
        if (cs[k] > 1.5f) {
            float* s = sums + (v0 + k) * NFEAT;
            float inv_c = cs[k];
            #pragma unroll
            for (int f = 0; f < NFEAT; f++)
                s[f] = __fdiv_rn(s[f], inv_c);
        }
    }
}

extern "C" void kernel_launch(void* const* d_in, const int* in_sizes, int n_in,
                              void* d_out, int out_size) {
    const float* pts = (const float*)d_in[0];
    float* out = (float*)d_out;

    const size_t n_sums = (size_t)BATCH * NV_ * NFEAT;   // 46,656,000
    float* sums = out;
    float* cnts = out + n_sums;

    // 1) Zero the whole output + write shape tail, one streaming kernel.
    {
        const int threads = 256;
        unsigned blocks = (N_DATA4 + threads - 1) / threads;
        zero_init_kernel<<<blocks, threads>>>((float4*)d_out, out);
    }

    // 2) Atomic scatter-add of kept points.
    {
        const int threads = 256;
        dim3 grid((NPTS + threads - 1) / threads, BATCH);
        scatter_kernel<<<grid, threads>>>(pts, sums, cnts);
    }

    // 3) Sparse divide for multi-point voxels.
    {
        const int threads = 256;
        unsigned n4 = (unsigned)((size_t)BATCH * NV_ / 4);
        finalize_kernel<<<(n4 + threads - 1) / threads, threads>>>(
            sums, (const float4*)cnts);
    }
}

// round 4
// speedup vs baseline: 1.1288x; 1.0525x over previous
#include <cuda_runtime.h>
#include <math.h>

// Problem constants (match reference)
#define BATCH 4
#define NPTS  300000
#define NX_   540
#define NY_   540
#define NZ_   8
#define NV_   (NX_ * NY_ * NZ_)          // 2,332,800
#define NFEAT 5

// Output layout (tuple flattened, all float32):
//   [0, BATCH*NV_*NFEAT)   voxel means (46,656,000)
//   [.., +BATCH*NV_)       counts       (9,331,200)
//   last 3                 shape {540, 540, 8}
#define N_DATA4 13996800u   // (BATCH*NV_*(NFEAT+1)) / 4

// ---------------------------------------------------------------------------
// Vector reduction helper: one L2 atomic op covering 8 bytes (sm_90+).
__device__ __forceinline__ void red_add_v2(float* addr, float a, float b) {
    asm volatile("red.global.add.v2.f32 [%0], {%1, %2};"
                 :: "l"(addr), "f"(a), "f"(b) : "memory");
}
__device__ __forceinline__ void red_add(float* addr, float a) {
    asm volatile("red.global.add.f32 [%0], %1;"
                 :: "l"(addr), "f"(a) : "memory");
}

// ---------------------------------------------------------------------------
__global__ void zero_init_kernel(float4* __restrict__ out4,
                                 float* __restrict__ out) {
    // 4 float4 per thread, stride-blockDim within block for coalescing.
    unsigned base = blockIdx.x * (blockDim.x * 4) + threadIdx.x;
    const float4 z4 = make_float4(0.f, 0.f, 0.f, 0.f);
    #pragma unroll
    for (int k = 0; k < 4; k++) {
        unsigned i = base + k * blockDim.x;
        if (i < N_DATA4) out4[i] = z4;
    }
    if (base == 0) {
        const size_t shape_off = (size_t)N_DATA4 * 4;
        out[shape_off + 0] = 540.0f;
        out[shape_off + 1] = 540.0f;
        out[shape_off + 2] = 8.0f;
    }
}

// ---------------------------------------------------------------------------
__device__ __forceinline__ void scatter_point(float x, float y, float z,
                                              float f3, float f4,
                                              float* __restrict__ sums,
                                              float* __restrict__ cnts,
                                              int b) {
    // keep = all(xyz >= LO) & all(xyz <= HI), inclusive both sides
    bool keep = (x >= -54.0f) & (x <= 54.0f) &
                (y >= -54.0f) & (y <= 54.0f) &
                (z >= -5.0f)  & (z <= 3.0f);
    if (!keep) return;

    // Reference (XLA) folds /VOX into multiply by the rounded reciprocal:
    // 1/0.2f -> exactly 5.0f. For kept points the operand is >= 0, so
    // truncation == floor.
    int cx = (int)((x + 54.0f) * 5.0f);
    int cy = (int)((y + 54.0f) * 5.0f);
    int cz = (int)(z + 5.0f);
    cx = min(max(cx, 0), NX_ - 1);
    cy = min(max(cy, 0), NY_ - 1);
    cz = min(max(cz, 0), NZ_ - 1);

    size_t lin = ((size_t)cz * NY_ + (size_t)cy) * NX_ + (size_t)cx;
    size_t v = (size_t)b * NV_ + lin;

    float* s = sums + v * NFEAT;
    if ((v & 1) == 0) {
        // s is 8B-aligned (20*v with v even -> 40k bytes)
        red_add_v2(s + 0, x, y);
        red_add_v2(s + 2, z, f3);
        red_add(s + 4, f4);
    } else {
        // s+1 is 8B-aligned
        red_add(s + 0, x);
        red_add_v2(s + 1, y, z);
        red_add_v2(s + 3, f3, f4);
    }
    red_add(cnts + v, 1.0f);
}

__global__ void scatter_kernel(const float4* __restrict__ pts4,
                               float* __restrict__ sums,
                               float* __restrict__ cnts) {
    // Each thread handles 4 consecutive points = 20 floats = 5 float4 loads.
    int t = blockIdx.x * blockDim.x + threadIdx.x;
    if (t >= NPTS / 4) return;
    int b = blockIdx.y;

    // batch base in float4s: b * NPTS * 5 / 4 (exactly divisible)
    const float4* p = pts4 + (size_t)b * (NPTS * NFEAT / 4) + (size_t)t * 5;
    float4 q0 = p[0];
    float4 q1 = p[1];
    float4 q2 = p[2];
    float4 q3 = p[3];
    float4 q4 = p[4];

    scatter_point(q0.x, q0.y, q0.z, q0.w, q1.x, sums, cnts, b);
    scatter_point(q1.y, q1.z, q1.w, q2.x, q2.y, sums, cnts, b);
    scatter_point(q2.z, q2.w, q3.x, q3.y, q3.z, sums, cnts, b);
    scatter_point(q3.w, q4.x, q4.y, q4.z, q4.w, sums, cnts, b);
}

// ---------------------------------------------------------------------------
// After zero-init: cnt==0 -> 0 already stored; cnt==1 -> sum/1 is already the
// mean. Only voxels with cnt>=2 need the divide.
__global__ void finalize_kernel(float* __restrict__ sums,
                                const float4* __restrict__ cnts4) {
    unsigned i = blockIdx.x * blockDim.x + threadIdx.x;
    const unsigned n4 = (unsigned)((size_t)BATCH * NV_ / 4);
    if (i >= n4) return;
    float4 c = cnts4[i];
    size_t v0 = (size_t)i * 4;
    float cs[4] = {c.x, c.y, c.z, c.w};
    #pragma unroll
    for (int k = 0; k < 4; k++) {
        if (cs[k] > 1.5f) {
            float* s = sums + (v0 + k) * NFEAT;
            #pragma unroll
            for (int f = 0; f < NFEAT; f++)
                s[f] = __fdiv_rn(s[f], cs[k]);
        }
    }
}

// ---------------------------------------------------------------------------
extern "C" void kernel_launch(void* const* d_in, const int* in_sizes, int n_in,
                              void* d_out, int out_size) {
    const float* pts = (const float*)d_in[0];
    float* out = (float*)d_out;

    const size_t n_sums = (size_t)BATCH * NV_ * NFEAT;   // 46,656,000
    float* sums = out;
    float* cnts = out + n_sums;

    // 1) Zero the whole output + write shape tail.
    {
        const int threads = 256;
        unsigned per_block = threads * 4;
        unsigned blocks = (N_DATA4 + per_block - 1) / per_block;
        zero_init_kernel<<<blocks, threads>>>((float4*)d_out, out);
    }

    // 2) Atomic scatter-add of kept points (4 points/thread, v2 reductions).
    {
        const int threads = 256;
        int groups = NPTS / 4;   // 75000
        dim3 grid((groups + threads - 1) / threads, BATCH);
        scatter_kernel<<<grid, threads>>>((const float4*)pts, sums, cnts);
    }

    // 3) Sparse divide for multi-point voxels.
    {
        const int threads = 256;
        unsigned n4 = (unsigned)((size_t)BATCH * NV_ / 4);
        finalize_kernel<<<(n4 + threads - 1) / threads, threads>>>(
            sums, (const float4*)cnts);
    }
}

// round 5
// speedup vs baseline: 1.2197x; 1.0805x over previous
#include <cuda_runtime.h>
#include <math.h>

// Problem constants (match reference)
#define BATCH 4
#define NPTS  300000
#define NX_   540
#define NY_   540
#define NZ_   8
#define NV_   (NX_ * NY_ * NZ_)          // 2,332,800
#define NFEAT 5

// Output layout (tuple flattened, all float32):
//   [0, BATCH*NV_*NFEAT)   voxel means (46,656,000)
//   [.., +BATCH*NV_)       counts       (9,331,200)
//   last 3                 shape {540, 540, 8}
//
// Per-batch regions: sums_b = 11,664,000 floats (46.6 MB), cnts_b = 2,332,800
// floats (9.3 MB). Together 56 MB < 126 MB L2: zero -> scatter -> finalize of
// one batch keeps all atomic targets L2-resident (the whole point of the
// batch-sequential structure).

#define SUMS_B   (NV_ * NFEAT)           // 11,664,000 floats per batch
#define SUMS_B4  (SUMS_B / 4)            //  2,916,000 float4
#define CNTS_B4  (NV_ / 4)               //    583,200 float4
#define ZERO_B4  (SUMS_B4 + CNTS_B4)     //  3,499,200 float4 per batch

// ---------------------------------------------------------------------------
__device__ __forceinline__ void red_add_v2(float* addr, float a, float b) {
    asm volatile("red.global.add.v2.f32 [%0], {%1, %2};"
                 :: "l"(addr), "f"(a), "f"(b) : "memory");
}
__device__ __forceinline__ void red_add(float* addr, float a) {
    asm volatile("red.global.add.f32 [%0], %1;"
                 :: "l"(addr), "f"(a) : "memory");
}

// ---------------------------------------------------------------------------
// Zero one batch's sums + counts regions (and optionally the 3-float shape
// tail). Leaves the 56 MB region dirty-resident in L2 for the scatter.
__global__ void zero_batch_kernel(float4* __restrict__ sums4,
                                  float4* __restrict__ cnts4,
                                  float* __restrict__ shape_tail) {
    unsigned base = blockIdx.x * (blockDim.x * 4) + threadIdx.x;
    const float4 z4 = make_float4(0.f, 0.f, 0.f, 0.f);
    #pragma unroll
    for (int k = 0; k < 4; k++) {
        unsigned i = base + k * blockDim.x;
        if (i < SUMS_B4) {
            sums4[i] = z4;
        } else if (i < ZERO_B4) {
            cnts4[i - SUMS_B4] = z4;
        }
    }
    if (shape_tail != nullptr && base == 0) {
        shape_tail[0] = 540.0f;
        shape_tail[1] = 540.0f;
        shape_tail[2] = 8.0f;
    }
}

// ---------------------------------------------------------------------------
__device__ __forceinline__ void scatter_point(float x, float y, float z,
                                              float f3, float f4,
                                              float* __restrict__ sums,
                                              float* __restrict__ cnts) {
    // keep = all(xyz >= LO) & all(xyz <= HI), inclusive both sides
    bool keep = (x >= -54.0f) & (x <= 54.0f) &
                (y >= -54.0f) & (y <= 54.0f) &
                (z >= -5.0f)  & (z <= 3.0f);
    if (!keep) return;

    // Reference (XLA) folds /VOX into multiply by the rounded reciprocal:
    // 1/0.2f -> exactly 5.0f. Kept points have non-negative operands, so
    // truncation == floor.
    int cx = (int)((x + 54.0f) * 5.0f);
    int cy = (int)((y + 54.0f) * 5.0f);
    int cz = (int)(z + 5.0f);
    cx = min(max(cx, 0), NX_ - 1);
    cy = min(max(cy, 0), NY_ - 1);
    cz = min(max(cz, 0), NZ_ - 1);

    unsigned lin = ((unsigned)cz * NY_ + (unsigned)cy) * NX_ + (unsigned)cx;

    float* s = sums + (size_t)lin * NFEAT;
    if ((lin & 1) == 0) {
        red_add_v2(s + 0, x, y);
        red_add_v2(s + 2, z, f3);
        red_add(s + 4, f4);
    } else {
        red_add(s + 0, x);
        red_add_v2(s + 1, y, z);
        red_add_v2(s + 3, f3, f4);
    }
    red_add(cnts + lin, 1.0f);
}

__global__ void scatter_kernel(const float4* __restrict__ pts4,
                               float* __restrict__ sums,
                               float* __restrict__ cnts) {
    // Each thread handles 4 consecutive points = 20 floats = 5 float4 loads.
    int t = blockIdx.x * blockDim.x + threadIdx.x;
    if (t >= NPTS / 4) return;

    const float4* p = pts4 + (size_t)t * 5;
    float4 q0 = p[0];
    float4 q1 = p[1];
    float4 q2 = p[2];
    float4 q3 = p[3];
    float4 q4 = p[4];

    scatter_point(q0.x, q0.y, q0.z, q0.w, q1.x, sums, cnts);
    scatter_point(q1.y, q1.z, q1.w, q2.x, q2.y, sums, cnts);
    scatter_point(q2.z, q2.w, q3.x, q3.y, q3.z, sums, cnts);
    scatter_point(q3.w, q4.x, q4.y, q4.z, q4.w, sums, cnts);
}

// ---------------------------------------------------------------------------
// After zero-init: cnt==0 -> 0 already stored; cnt==1 -> sum/1 is already the
// mean. Only voxels with cnt>=2 need the divide. Runs while batch region is
// still L2-resident.
__global__ void finalize_kernel(float* __restrict__ sums,
                                const float4* __restrict__ cnts4) {
    unsigned i = blockIdx.x * blockDim.x + threadIdx.x;
    if (i >= CNTS_B4) return;
    float4 c = cnts4[i];
    size_t v0 = (size_t)i * 4;
    float cs[4] = {c.x, c.y, c.z, c.w};
    #pragma unroll
    for (int k = 0; k < 4; k++) {
        if (cs[k] > 1.5f) {
            float* s = sums + (v0 + k) * NFEAT;
            #pragma unroll
            for (int f = 0; f < NFEAT; f++)
                s[f] = __fdiv_rn(s[f], cs[k]);
        }
    }
}

// ---------------------------------------------------------------------------
extern "C" void kernel_launch(void* const* d_in, const int* in_sizes, int n_in,
                              void* d_out, int out_size) {
    const float* pts = (const float*)d_in[0];
    float* out = (float*)d_out;

    const size_t n_sums = (size_t)BATCH * SUMS_B;        // 46,656,000
    float* sums_base = out;
    float* cnts_base = out + n_sums;
    float* shape_tail = out + n_sums + (size_t)BATCH * NV_;

    const int threads = 256;
    const unsigned zero_blocks = (ZERO_B4 + threads * 4 - 1) / (threads * 4);
    const int scatter_groups = NPTS / 4;                 // 75,000
    const unsigned scatter_blocks = (scatter_groups + threads - 1) / threads;
    const unsigned fin_blocks = (CNTS_B4 + threads - 1) / threads;

    for (int b = 0; b < BATCH; b++) {
        float* sums_b = sums_base + (size_t)b * SUMS_B;
        float* cnts_b = cnts_base + (size_t)b * NV_;
        const float4* pts_b =
            (const float4*)(pts + (size_t)b * NPTS * NFEAT);

        zero_batch_kernel<<<zero_blocks, threads>>>(
            (float4*)sums_b, (float4*)cnts_b, b == 0 ? shape_tail : nullptr);

        scatter_kernel<<<scatter_blocks, threads>>>(pts_b, sums_b, cnts_b);

        finalize_kernel<<<fin_blocks, threads>>>(sums_b, (const float4*)cnts_b);
    }
}

// round 6
// speedup vs baseline: 1.3383x; 1.0973x over previous
#include <cuda_runtime.h>
#include <math.h>

// Problem constants (match reference)
#define BATCH 4
#define NPTS  300000
#define NX_   540
#define NY_   540
#define NZ_   8
#define NV_   (NX_ * NY_ * NZ_)          // 2,332,800
#define NFEAT 5

// Output layout (tuple flattened, all float32):
//   [0, BATCH*NV_*NFEAT)   voxel means (46,656,000)
//   [.., +BATCH*NV_)       counts       (9,331,200)
//   last 3                 shape {540, 540, 8}

#define SUMS_B   (NV_ * NFEAT)           // 11,664,000 floats per batch
#define SUMS_B4  (SUMS_B / 4)            //  2,916,000 float4
#define CNTS_B4  (NV_ / 4)               //    583,200 float4
#define ZERO_B4  (SUMS_B4 + CNTS_B4)     //  3,499,200 float4 per batch

#define THREADS      256
#define SCAT_GROUPS  (NPTS / 4)                                   // 75,000
#define SCAT_BLOCKS  ((SCAT_GROUPS + THREADS - 1) / THREADS)      // 293
#define FIN_BLOCKS   ((CNTS_B4 + THREADS - 1) / THREADS)          // 2,279
#define ZERO_BLOCKS  ((ZERO_B4 + THREADS * 4 - 1) / (THREADS * 4))// 3,418

// ---------------------------------------------------------------------------
__device__ __forceinline__ void red_add_v2(float* addr, float a, float b) {
    asm volatile("red.global.add.v2.f32 [%0], {%1, %2};"
                 :: "l"(addr), "f"(a), "f"(b) : "memory");
}
__device__ __forceinline__ void red_add(float* addr, float a) {
    asm volatile("red.global.add.f32 [%0], %1;"
                 :: "l"(addr), "f"(a) : "memory");
}

// ---------------------------------------------------------------------------
__device__ __forceinline__ void scatter_point(float x, float y, float z,
                                              float f3, float f4,
                                              float* __restrict__ sums,
                                              float* __restrict__ cnts) {
    // keep = all(xyz >= LO) & all(xyz <= HI), inclusive both sides
    bool keep = (x >= -54.0f) & (x <= 54.0f) &
                (y >= -54.0f) & (y <= 54.0f) &
                (z >= -5.0f)  & (z <= 3.0f);
    if (!keep) return;

    // Reference (XLA) folds /VOX into multiply by the rounded reciprocal:
    // 1/0.2f -> exactly 5.0f. Kept points have non-negative operands, so
    // truncation == floor.
    int cx = (int)((x + 54.0f) * 5.0f);
    int cy = (int)((y + 54.0f) * 5.0f);
    int cz = (int)(z + 5.0f);
    cx = min(max(cx, 0), NX_ - 1);
    cy = min(max(cy, 0), NY_ - 1);
    cz = min(max(cz, 0), NZ_ - 1);

    unsigned lin = ((unsigned)cz * NY_ + (unsigned)cy) * NX_ + (unsigned)cx;

    float* s = sums + (size_t)lin * NFEAT;
    if ((lin & 1) == 0) {
        red_add_v2(s + 0, x, y);
        red_add_v2(s + 2, z, f3);
        red_add(s + 4, f4);
    } else {
        red_add(s + 0, x);
        red_add_v2(s + 1, y, z);
        red_add_v2(s + 3, f3, f4);
    }
    red_add(cnts + lin, 1.0f);
}

// ---------------------------------------------------------------------------
// Fused "mega" kernel: block-range dispatch over up to three independent
// roles operating on DIFFERENT batches (disjoint memory regions):
//   [0, n_scat)                : scatter batch b   (LTS atomic path)
//   [n_scat, n_scat+n_fin)     : finalize batch b-1 (L2 read + sparse RMW)
//   [n_scat+n_fin, ..+n_zero)  : zero batch b+1     (L2 write / DRAM writeback)
// Scatter first so the long pole starts in wave 0.
__global__ void __launch_bounds__(THREADS)
mega_kernel(const float4* __restrict__ scat_pts,
            float* __restrict__ scat_sums, float* __restrict__ scat_cnts,
            unsigned n_scat,
            float* __restrict__ fin_sums, const float4* __restrict__ fin_cnts4,
            unsigned n_fin,
            float4* __restrict__ zero_sums4, float4* __restrict__ zero_cnts4,
            unsigned n_zero,
            float* __restrict__ shape_tail) {
    unsigned bid = blockIdx.x;

    if (bid < n_scat) {
        // ---- scatter role: 4 consecutive points = 5 float4 loads ----
        unsigned t = bid * THREADS + threadIdx.x;
        if (t >= SCAT_GROUPS) return;
        const float4* p = scat_pts + (size_t)t * 5;
        float4 q0 = p[0];
        float4 q1 = p[1];
        float4 q2 = p[2];
        float4 q3 = p[3];
        float4 q4 = p[4];
        scatter_point(q0.x, q0.y, q0.z, q0.w, q1.x, scat_sums, scat_cnts);
        scatter_point(q1.y, q1.z, q1.w, q2.x, q2.y, scat_sums, scat_cnts);
        scatter_point(q2.z, q2.w, q3.x, q3.y, q3.z, scat_sums, scat_cnts);
        scatter_point(q3.w, q4.x, q4.y, q4.z, q4.w, scat_sums, scat_cnts);
        return;
    }
    bid -= n_scat;

    if (bid < n_fin) {
        // ---- finalize role: cnt==0/1 already correct after zero+scatter;
        //      only cnt>=2 voxels need the divide ----
        unsigned i = bid * THREADS + threadIdx.x;
        if (i >= CNTS_B4) return;
        float4 c = fin_cnts4[i];
        size_t v0 = (size_t)i * 4;
        float cs[4] = {c.x, c.y, c.z, c.w};
        #pragma unroll
        for (int k = 0; k < 4; k++) {
            if (cs[k] > 1.5f) {
                float* s = fin_sums + (v0 + k) * NFEAT;
                #pragma unroll
                for (int f = 0; f < NFEAT; f++)
                    s[f] = __fdiv_rn(s[f], cs[k]);
            }
        }
        return;
    }
    bid -= n_fin;

    if (bid < n_zero) {
        // ---- zero role: 4 float4 per thread across sums then counts ----
        unsigned base = bid * (THREADS * 4) + threadIdx.x;
        const float4 z4 = make_float4(0.f, 0.f, 0.f, 0.f);
        #pragma unroll
        for (int k = 0; k < 4; k++) {
            unsigned i = base + k * THREADS;
            if (i < SUMS_B4) {
                zero_sums4[i] = z4;
            } else if (i < ZERO_B4) {
                zero_cnts4[i - SUMS_B4] = z4;
            }
        }
        if (shape_tail != nullptr && base == 0) {
            shape_tail[0] = 540.0f;
            shape_tail[1] = 540.0f;
            shape_tail[2] = 8.0f;
        }
    }
}

// ---------------------------------------------------------------------------
extern "C" void kernel_launch(void* const* d_in, const int* in_sizes, int n_in,
                              void* d_out, int out_size) {
    const float* pts = (const float*)d_in[0];
    float* out = (float*)d_out;

    const size_t n_sums = (size_t)BATCH * SUMS_B;        // 46,656,000
    float* sums_base = out;
    float* cnts_base = out + n_sums;
    float* shape_tail = out + n_sums + (size_t)BATCH * NV_;

    auto sums_b = [&](int b) { return sums_base + (size_t)b * SUMS_B; };
    auto cnts_b = [&](int b) { return cnts_base + (size_t)b * NV_; };
    auto pts_b  = [&](int b) {
        return (const float4*)(pts + (size_t)b * NPTS * NFEAT);
    };

    // Software pipeline, one fused launch per stage:
    //   stage s: scatter(s), finalize(s-1), zero(s+1)   [roles in range]
    // s = -1 is the prologue (zero(0) only); s = 4,5 drain fin(3).
    for (int s = -1; s <= 4; s++) {
        int b_scat = s;          // valid 0..3
        int b_fin  = s - 1;      // valid 0..3
        int b_zero = s + 1;      // valid 0..3

        bool has_scat = (b_scat >= 0 && b_scat < BATCH);
        bool has_fin  = (b_fin  >= 0 && b_fin  < BATCH);
        bool has_zero = (b_zero >= 0 && b_zero < BATCH);

        unsigned n_scat = has_scat ? SCAT_BLOCKS : 0;
        unsigned n_fin  = has_fin  ? FIN_BLOCKS  : 0;
        unsigned n_zero = has_zero ? ZERO_BLOCKS : 0;
        unsigned total = n_scat + n_fin + n_zero;
        if (total == 0) continue;

        mega_kernel<<<total, THREADS>>>(
            has_scat ? pts_b(b_scat) : nullptr,
            has_scat ? sums_b(b_scat) : nullptr,
            has_scat ? cnts_b(b_scat) : nullptr,
            n_scat,
            has_fin ? sums_b(b_fin) : nullptr,
            has_fin ? (const float4*)cnts_b(b_fin) : nullptr,
            n_fin,
            has_zero ? (float4*)sums_b(b_zero) : nullptr,
            has_zero ? (float4*)cnts_b(b_zero) : nullptr,
            n_zero,
            (b_zero == 0) ? shape_tail : nullptr);
    }
}